// round 2
// baseline (speedup 1.0000x reference)
#include <cuda_runtime.h>
#include <cuda_bf16.h>
#include <cstdint>

// Problem constants
#define BB 4096
#define SS 64
#define EE 128
#define HH 256
#define CC 18

#define BM 32      // batch rows per block
#define KT 16      // k-tile
#define NTHREADS 256

// Scratch (allocation-free rule: static __device__ arrays)
__device__ float g_xw[SS * BB * HH];   // [t][b][h], 256 MB
__device__ float g_last[BB * HH];      // final hidden per row, 4 MB

// ---------------------------------------------------------------------------
// Kernel 1: xW[t][b][h] = b_ih[h] + sum_e emb[x_in[b][t]][e] * W_ih[h][e]
// grid: (B/BM, S), 256 threads
// ---------------------------------------------------------------------------
__global__ __launch_bounds__(NTHREADS) void proj_kernel(
    const int* __restrict__ x_in,
    const float* __restrict__ emb,
    const float* __restrict__ W_ih,
    const float* __restrict__ b_ih)
{
    __shared__ float Asm[BM][EE];   // gathered embedding rows (16 KB)
    __shared__ float Wt[KT][HH];    // W_ih k-tile, transposed (16 KB)

    const int t   = blockIdx.y;
    const int b0  = blockIdx.x * BM;
    const int tid = threadIdx.x;

    // Gather 32 embedding rows: 8 threads/row, 16 floats/thread
    {
        const int r   = tid >> 3;
        const int seg = tid & 7;
        const int idx = x_in[(b0 + r) * SS + t];
        const float4* src = reinterpret_cast<const float4*>(emb + (size_t)idx * EE + seg * 16);
        float4* dst = reinterpret_cast<float4*>(&Asm[r][seg * 16]);
#pragma unroll
        for (int q = 0; q < 4; q++) dst[q] = src[q];
    }

    const int r_t = tid >> 5;   // 0..7  (warp id)
    const int c_t = tid & 31;   // 0..31

    float acc[4][8];
    {
        float4 bl = *reinterpret_cast<const float4*>(b_ih + c_t * 8);
        float4 bh = *reinterpret_cast<const float4*>(b_ih + c_t * 8 + 4);
        float bias[8] = {bl.x, bl.y, bl.z, bl.w, bh.x, bh.y, bh.z, bh.w};
#pragma unroll
        for (int i = 0; i < 4; i++)
#pragma unroll
            for (int j = 0; j < 8; j++) acc[i][j] = bias[j];
    }

    const int kk4   = tid & 3;
    const int cbase = tid >> 2;

    for (int k0 = 0; k0 < EE; k0 += KT) {
        __syncthreads();
        // load W_ih tile transposed: Wt[kk][c] = W_ih[c][k0+kk]
#pragma unroll
        for (int q = 0; q < 4; q++) {
            const int c = cbase + 64 * q;
            float4 v = *reinterpret_cast<const float4*>(W_ih + (size_t)c * EE + k0 + kk4 * 4);
            Wt[kk4 * 4 + 0][c] = v.x;
            Wt[kk4 * 4 + 1][c] = v.y;
            Wt[kk4 * 4 + 2][c] = v.z;
            Wt[kk4 * 4 + 3][c] = v.w;
        }
        __syncthreads();
#pragma unroll
        for (int kk = 0; kk < KT; kk++) {
            float a[4];
#pragma unroll
            for (int i = 0; i < 4; i++) a[i] = Asm[r_t * 4 + i][k0 + kk];
            float w[8];
            *reinterpret_cast<float4*>(w)     = *reinterpret_cast<const float4*>(&Wt[kk][c_t * 8]);
            *reinterpret_cast<float4*>(w + 4) = *reinterpret_cast<const float4*>(&Wt[kk][c_t * 8 + 4]);
#pragma unroll
            for (int i = 0; i < 4; i++)
#pragma unroll
                for (int j = 0; j < 8; j++) acc[i][j] += a[i] * w[j];
        }
    }

    // write out: g_xw[(t*B + b)*H + h]
#pragma unroll
    for (int i = 0; i < 4; i++) {
        float* dst = &g_xw[((size_t)t * BB + b0 + r_t * 4 + i) * HH + c_t * 8];
        *reinterpret_cast<float4*>(dst)     = *reinterpret_cast<float4*>(&acc[i][0]);
        *reinterpret_cast<float4*>(dst + 4) = *reinterpret_cast<float4*>(&acc[i][4]);
    }
}

// ---------------------------------------------------------------------------
// Kernel 2: RNN scan. Each block owns 32 batch rows for all 64 steps.
// h_new = tanh(xw[t] + h @ W_hh^T + b_hh); saves h at t == len-1.
// grid: B/BM, 256 threads
// ---------------------------------------------------------------------------
__global__ __launch_bounds__(NTHREADS) void rnn_kernel(
    const int* __restrict__ x_lengths,
    const float* __restrict__ W_hh,
    const float* __restrict__ b_hh)
{
    __shared__ float Hs[BM][HH];    // current hidden (32 KB)
    __shared__ float Wt[KT][HH];    // W_hh k-tile (16 KB)

    const int b0  = blockIdx.x * BM;
    const int tid = threadIdx.x;
    const int r_t = tid >> 5;
    const int c_t = tid & 31;

    // zero h0
    for (int i = tid; i < BM * HH; i += NTHREADS) (&Hs[0][0])[i] = 0.0f;

    float bbh[8];
    {
        float4 bl = *reinterpret_cast<const float4*>(b_hh + c_t * 8);
        float4 bh = *reinterpret_cast<const float4*>(b_hh + c_t * 8 + 4);
        bbh[0]=bl.x; bbh[1]=bl.y; bbh[2]=bl.z; bbh[3]=bl.w;
        bbh[4]=bh.x; bbh[5]=bh.y; bbh[6]=bh.z; bbh[7]=bh.w;
    }
    int rl[4];
#pragma unroll
    for (int i = 0; i < 4; i++) rl[i] = x_lengths[b0 + r_t * 4 + i];

    const int kk4   = tid & 3;
    const int cbase = tid >> 2;

    __syncthreads();

    for (int t = 0; t < SS; t++) {
        float acc[4][8];
        // init accumulator from precomputed input projection (includes b_ih)
#pragma unroll
        for (int i = 0; i < 4; i++) {
            const float* xr = &g_xw[((size_t)t * BB + b0 + r_t * 4 + i) * HH + c_t * 8];
            *reinterpret_cast<float4*>(&acc[i][0]) = *reinterpret_cast<const float4*>(xr);
            *reinterpret_cast<float4*>(&acc[i][4]) = *reinterpret_cast<const float4*>(xr + 4);
        }

        for (int k0 = 0; k0 < HH; k0 += KT) {
            __syncthreads();
#pragma unroll
            for (int q = 0; q < 4; q++) {
                const int c = cbase + 64 * q;
                float4 v = *reinterpret_cast<const float4*>(W_hh + (size_t)c * HH + k0 + kk4 * 4);
                Wt[kk4 * 4 + 0][c] = v.x;
                Wt[kk4 * 4 + 1][c] = v.y;
                Wt[kk4 * 4 + 2][c] = v.z;
                Wt[kk4 * 4 + 3][c] = v.w;
            }
            __syncthreads();
#pragma unroll
            for (int kk = 0; kk < KT; kk++) {
                float a[4];
#pragma unroll
                for (int i = 0; i < 4; i++) a[i] = Hs[r_t * 4 + i][k0 + kk];
                float w[8];
                *reinterpret_cast<float4*>(w)     = *reinterpret_cast<const float4*>(&Wt[kk][c_t * 8]);
                *reinterpret_cast<float4*>(w + 4) = *reinterpret_cast<const float4*>(&Wt[kk][c_t * 8 + 4]);
#pragma unroll
                for (int i = 0; i < 4; i++)
#pragma unroll
                    for (int j = 0; j < 8; j++) acc[i][j] += a[i] * w[j];
            }
        }
        __syncthreads();  // all reads of Hs done before overwriting

#pragma unroll
        for (int i = 0; i < 4; i++) {
            float hv[8];
#pragma unroll
            for (int j = 0; j < 8; j++) hv[j] = tanhf(acc[i][j] + bbh[j]);
            float* hd = &Hs[r_t * 4 + i][c_t * 8];
            *reinterpret_cast<float4*>(hd)     = *reinterpret_cast<float4*>(&hv[0]);
            *reinterpret_cast<float4*>(hd + 4) = *reinterpret_cast<float4*>(&hv[4]);
            if (t == rl[i] - 1) {
                float* dst = &g_last[(size_t)(b0 + r_t * 4 + i) * HH + c_t * 8];
                *reinterpret_cast<float4*>(dst)     = *reinterpret_cast<float4*>(&hv[0]);
                *reinterpret_cast<float4*>(dst + 4) = *reinterpret_cast<float4*>(&hv[4]);
            }
        }
    }
}

// ---------------------------------------------------------------------------
// Kernel 3: out = relu(last @ W1^T + b1) @ W2^T + b2
// grid: B/BM, 256 threads
// ---------------------------------------------------------------------------
__global__ __launch_bounds__(NTHREADS) void fc_kernel(
    const float* __restrict__ W1,
    const float* __restrict__ b1,
    const float* __restrict__ W2,
    const float* __restrict__ b2,
    float* __restrict__ out)
{
    __shared__ float Asm[BM][HH];   // last hidden, then relu(y)
    __shared__ float Wt[KT][HH];

    const int b0  = blockIdx.x * BM;
    const int tid = threadIdx.x;
    const int r_t = tid >> 5;
    const int c_t = tid & 31;

    for (int i = tid; i < BM * HH; i += NTHREADS)
        (&Asm[0][0])[i] = g_last[(size_t)b0 * HH + i];

    float acc[4][8];
    {
        float4 bl = *reinterpret_cast<const float4*>(b1 + c_t * 8);
        float4 bh = *reinterpret_cast<const float4*>(b1 + c_t * 8 + 4);
        float bias[8] = {bl.x, bl.y, bl.z, bl.w, bh.x, bh.y, bh.z, bh.w};
#pragma unroll
        for (int i = 0; i < 4; i++)
#pragma unroll
            for (int j = 0; j < 8; j++) acc[i][j] = bias[j];
    }

    const int kk4   = tid & 3;
    const int cbase = tid >> 2;

    for (int k0 = 0; k0 < HH; k0 += KT) {
        __syncthreads();
#pragma unroll
        for (int q = 0; q < 4; q++) {
            const int c = cbase + 64 * q;
            float4 v = *reinterpret_cast<const float4*>(W1 + (size_t)c * HH + k0 + kk4 * 4);
            Wt[kk4 * 4 + 0][c] = v.x;
            Wt[kk4 * 4 + 1][c] = v.y;
            Wt[kk4 * 4 + 2][c] = v.z;
            Wt[kk4 * 4 + 3][c] = v.w;
        }
        __syncthreads();
#pragma unroll
        for (int kk = 0; kk < KT; kk++) {
            float a[4];
#pragma unroll
            for (int i = 0; i < 4; i++) a[i] = Asm[r_t * 4 + i][k0 + kk];
            float w[8];
            *reinterpret_cast<float4*>(w)     = *reinterpret_cast<const float4*>(&Wt[kk][c_t * 8]);
            *reinterpret_cast<float4*>(w + 4) = *reinterpret_cast<const float4*>(&Wt[kk][c_t * 8 + 4]);
#pragma unroll
            for (int i = 0; i < 4; i++)
#pragma unroll
                for (int j = 0; j < 8; j++) acc[i][j] += a[i] * w[j];
        }
    }
    __syncthreads();  // done reading Asm (last hidden)

    // relu, write y back into Asm
#pragma unroll
    for (int i = 0; i < 4; i++) {
        float yv[8];
#pragma unroll
        for (int j = 0; j < 8; j++) yv[j] = fmaxf(acc[i][j], 0.0f);
        float* yd = &Asm[r_t * 4 + i][c_t * 8];
        *reinterpret_cast<float4*>(yd)     = *reinterpret_cast<float4*>(&yv[0]);
        *reinterpret_cast<float4*>(yd + 4) = *reinterpret_cast<float4*>(&yv[4]);
    }
    __syncthreads();

    // layer 2: out[r][c] = b2[c] + sum_k y[r][k] * W2[c][k]
    for (int e = tid; e < BM * CC; e += NTHREADS) {
        const int r = e / CC;
        const int c = e % CC;
        const float4* yv = reinterpret_cast<const float4*>(&Asm[r][0]);
        const float4* wv = reinterpret_cast<const float4*>(W2 + (size_t)c * HH);
        float s = b2[c];
#pragma unroll 8
        for (int k = 0; k < HH / 4; k++) {
            float4 a = yv[k];
            float4 w = wv[k];
            s += a.x * w.x + a.y * w.y + a.z * w.z + a.w * w.w;
        }
        out[(size_t)(b0 + r) * CC + c] = s;
    }
}

// ---------------------------------------------------------------------------
extern "C" void kernel_launch(void* const* d_in, const int* in_sizes, int n_in,
                              void* d_out, int out_size)
{
    const int*   x_in  = (const int*)  d_in[0];
    const int*   x_len = (const int*)  d_in[1];
    const float* emb   = (const float*)d_in[2];
    const float* W_ih  = (const float*)d_in[3];
    const float* W_hh  = (const float*)d_in[4];
    const float* b_ih  = (const float*)d_in[5];
    const float* b_hh  = (const float*)d_in[6];
    const float* W1    = (const float*)d_in[7];
    const float* b1    = (const float*)d_in[8];
    const float* W2    = (const float*)d_in[9];
    const float* b2    = (const float*)d_in[10];
    float* out = (float*)d_out;

    dim3 gp(BB / BM, SS);
    proj_kernel<<<gp, NTHREADS>>>(x_in, emb, W_ih, b_ih);
    rnn_kernel<<<BB / BM, NTHREADS>>>(x_len, W_hh, b_hh);
    fc_kernel<<<BB / BM, NTHREADS>>>(W1, b1, W2, b2, out);
}

// round 3
// speedup vs baseline: 1.2557x; 1.2557x over previous
#include <cuda_runtime.h>
#include <cuda_bf16.h>
#include <cstdint>

// Problem constants
#define VV 10000
#define BB 4096
#define SS 64
#define EE 128
#define HH 256
#define CC 18

#define BM 32      // batch rows per rnn block
#define NTHREADS 256

// Scratch (allocation-free rule: static __device__ arrays)
__device__ float g_embw[VV * HH];      // embW[v][h] = b_ih + emb[v] @ W_ih^T  (10.24 MB)
__device__ float g_whhT[HH * HH];      // W_hh transposed: [k][c]              (256 KB)
__device__ float g_last[BB * HH];      // final hidden per row                 (4 MB)

__device__ __forceinline__ float fast_tanh(float x) {
    // 1 - 2/(e^{2x}+1): correct at both saturations (e->inf => 1, e->0 => -1)
    float e = __expf(2.0f * x);
    return 1.0f - 2.0f / (e + 1.0f);
}

// ---------------------------------------------------------------------------
// Kernel 0: transpose W_hh (256x256) -> g_whhT[k][c] = W_hh[c][k]
// grid 64, 256 threads (32x32 tiles, 32x8 thread layout)
// ---------------------------------------------------------------------------
__global__ __launch_bounds__(NTHREADS) void transpose_whh_kernel(const float* __restrict__ W)
{
    __shared__ float tile[32][33];
    const int bx = blockIdx.x & 7;        // column tile
    const int by = blockIdx.x >> 3;       // row tile
    const int lx = threadIdx.x & 31;
    const int ly = threadIdx.x >> 5;      // 0..7
#pragma unroll
    for (int q = 0; q < 32; q += 8)
        tile[ly + q][lx] = W[(by * 32 + ly + q) * HH + bx * 32 + lx];
    __syncthreads();
#pragma unroll
    for (int q = 0; q < 32; q += 8)
        g_whhT[(bx * 32 + ly + q) * HH + by * 32 + lx] = tile[lx][ly + q];
}

// ---------------------------------------------------------------------------
// Kernel 1: embW[v][h] = b_ih[h] + sum_e emb[v][e] * W_ih[h][e]
// grid ceil(V/32)=313, 256 threads, 4x8 micro-tile
// ---------------------------------------------------------------------------
__global__ __launch_bounds__(NTHREADS) void embw_kernel(
    const float* __restrict__ emb,
    const float* __restrict__ W_ih,
    const float* __restrict__ b_ih)
{
    __shared__ float Asm[BM][EE];   // 32 emb rows (16 KB)
    __shared__ float Wt[16][HH];    // W_ih k-tile transposed (16 KB)

    const int b0  = blockIdx.x * BM;
    const int tid = threadIdx.x;

    // stage 32 emb rows (clamped for tail block)
    {
        const int r   = tid >> 3;
        const int seg = tid & 7;
        int v = b0 + r; if (v >= VV) v = VV - 1;
        const float4* src = reinterpret_cast<const float4*>(emb + (size_t)v * EE + seg * 16);
        float4* dst = reinterpret_cast<float4*>(&Asm[r][seg * 16]);
#pragma unroll
        for (int q = 0; q < 4; q++) dst[q] = src[q];
    }

    const int r_t = tid >> 5;
    const int c_t = tid & 31;

    float acc[4][8];
    {
        float4 bl = *reinterpret_cast<const float4*>(b_ih + c_t * 8);
        float4 bh = *reinterpret_cast<const float4*>(b_ih + c_t * 8 + 4);
        float bias[8] = {bl.x, bl.y, bl.z, bl.w, bh.x, bh.y, bh.z, bh.w};
#pragma unroll
        for (int i = 0; i < 4; i++)
#pragma unroll
            for (int j = 0; j < 8; j++) acc[i][j] = bias[j];
    }

    const int kk4   = tid & 3;
    const int cbase = tid >> 2;

    for (int k0 = 0; k0 < EE; k0 += 16) {
        __syncthreads();
#pragma unroll
        for (int q = 0; q < 4; q++) {
            const int c = cbase + 64 * q;
            float4 v = *reinterpret_cast<const float4*>(W_ih + (size_t)c * EE + k0 + kk4 * 4);
            Wt[kk4 * 4 + 0][c] = v.x;
            Wt[kk4 * 4 + 1][c] = v.y;
            Wt[kk4 * 4 + 2][c] = v.z;
            Wt[kk4 * 4 + 3][c] = v.w;
        }
        __syncthreads();
#pragma unroll
        for (int kk = 0; kk < 16; kk++) {
            float a[4];
#pragma unroll
            for (int i = 0; i < 4; i++) a[i] = Asm[r_t * 4 + i][k0 + kk];
            float w[8];
            *reinterpret_cast<float4*>(w)     = *reinterpret_cast<const float4*>(&Wt[kk][c_t * 8]);
            *reinterpret_cast<float4*>(w + 4) = *reinterpret_cast<const float4*>(&Wt[kk][c_t * 8 + 4]);
#pragma unroll
            for (int i = 0; i < 4; i++)
#pragma unroll
                for (int j = 0; j < 8; j++) acc[i][j] += a[i] * w[j];
        }
    }

#pragma unroll
    for (int i = 0; i < 4; i++) {
        const int v = b0 + r_t * 4 + i;
        if (v < VV) {
            float* dst = g_embw + (size_t)v * HH + c_t * 8;
            *reinterpret_cast<float4*>(dst)     = *reinterpret_cast<float4*>(&acc[i][0]);
            *reinterpret_cast<float4*>(dst + 4) = *reinterpret_cast<float4*>(&acc[i][4]);
        }
    }
}

// ---------------------------------------------------------------------------
// Kernel 2: RNN scan. Each block owns 32 batch rows for all 64 steps.
// h_new = tanh(embW[x_in[b][t]] + h @ W_hh^T + b_hh); save h at t == len-1.
// grid 128, 256 threads, 8x4 micro-tile, KT=32 double-buffered tiles.
// Dynamic SMEM: Hs[32*256] + Wt[2*32*256] = 96 KB
// ---------------------------------------------------------------------------
__global__ __launch_bounds__(NTHREADS) void rnn_kernel(
    const int* __restrict__ x_in,
    const int* __restrict__ x_lengths,
    const float* __restrict__ b_hh)
{
    extern __shared__ float smem[];
    float* Hs = smem;                 // [32][256]
    float* Wt = smem + BM * HH;       // [2][32][256]

    const int b0   = blockIdx.x * BM;
    const int tid  = threadIdx.x;
    const int r0   = (tid >> 6) * 8;        // 8 rows per thread
    const int col0 = (tid & 63) * 4;        // 4 cols per thread

    // zero h0
    for (int i = tid; i < BM * HH; i += NTHREADS) Hs[i] = 0.0f;

    float4 bb = *reinterpret_cast<const float4*>(b_hh + col0);
    int rl[8];
#pragma unroll
    for (int i = 0; i < 8; i++) rl[i] = x_lengths[b0 + r0 + i];

    // preload W tile 0 into buffer 0 (tile j always lives in buffer j&1)
    {
#pragma unroll
        for (int p = 0; p < 8; p++) {
            const int f4 = tid + NTHREADS * p;
            float4 v = *reinterpret_cast<const float4*>(
                g_whhT + (size_t)((f4 >> 6) * HH) + (f4 & 63) * 4);
            *reinterpret_cast<float4*>(Wt + (f4 >> 6) * HH + (f4 & 63) * 4) = v;
        }
    }
    __syncthreads();

    for (int t = 0; t < SS; t++) {
        // acc init = gathered input projection (includes b_ih)
        float acc[8][4];
#pragma unroll
        for (int i = 0; i < 8; i++) {
            const int idx = x_in[(b0 + r0 + i) * SS + t];
            float4 v = *reinterpret_cast<const float4*>(g_embw + (size_t)idx * HH + col0);
            acc[i][0] = v.x; acc[i][1] = v.y; acc[i][2] = v.z; acc[i][3] = v.w;
        }

#pragma unroll
        for (int j = 0; j < 8; j++) {              // 8 tiles of KT=32
            const int buf = j & 1;
            const int jn  = (j + 1) & 7;           // cyclic: tile 7 prefetches tile 0

            // register-staged prefetch of next tile
            float4 ld[8];
#pragma unroll
            for (int p = 0; p < 8; p++) {
                const int f4 = tid + NTHREADS * p;
                ld[p] = *reinterpret_cast<const float4*>(
                    g_whhT + (size_t)((jn * 32 + (f4 >> 6)) * HH) + (f4 & 63) * 4);
            }

            // compute tile j
            const float* Wb = Wt + buf * (32 * HH);
#pragma unroll
            for (int kc = 0; kc < 8; kc++) {       // chunks of 4 k
                float a[8][4];
#pragma unroll
                for (int i = 0; i < 8; i++)
                    *reinterpret_cast<float4*>(a[i]) = *reinterpret_cast<const float4*>(
                        Hs + (r0 + i) * HH + j * 32 + kc * 4);
                float w[4][4];
#pragma unroll
                for (int m = 0; m < 4; m++)
                    *reinterpret_cast<float4*>(w[m]) = *reinterpret_cast<const float4*>(
                        Wb + (kc * 4 + m) * HH + col0);
#pragma unroll
                for (int i = 0; i < 8; i++)
#pragma unroll
                    for (int m = 0; m < 4; m++)
#pragma unroll
                        for (int c = 0; c < 4; c++)
                            acc[i][c] += a[i][m] * w[m][c];
            }

            // store prefetched tile into the other buffer
            float* Wd = Wt + (buf ^ 1) * (32 * HH);
#pragma unroll
            for (int p = 0; p < 8; p++) {
                const int f4 = tid + NTHREADS * p;
                *reinterpret_cast<float4*>(Wd + (f4 >> 6) * HH + (f4 & 63) * 4) = ld[p];
            }
            __syncthreads();
        }

        // h update
#pragma unroll
        for (int i = 0; i < 8; i++) {
            float4 hv;
            hv.x = fast_tanh(acc[i][0] + bb.x);
            hv.y = fast_tanh(acc[i][1] + bb.y);
            hv.z = fast_tanh(acc[i][2] + bb.z);
            hv.w = fast_tanh(acc[i][3] + bb.w);
            *reinterpret_cast<float4*>(Hs + (r0 + i) * HH + col0) = hv;
            if (t == rl[i] - 1)
                *reinterpret_cast<float4*>(g_last + (size_t)(b0 + r0 + i) * HH + col0) = hv;
        }
        __syncthreads();
    }
}

// ---------------------------------------------------------------------------
// Kernel 3: out = relu(last @ W1^T + b1) @ W2^T + b2
// grid 128, 256 threads
// ---------------------------------------------------------------------------
__global__ __launch_bounds__(NTHREADS) void fc_kernel(
    const float* __restrict__ W1,
    const float* __restrict__ b1,
    const float* __restrict__ W2,
    const float* __restrict__ b2,
    float* __restrict__ out)
{
    __shared__ float Asm[BM][HH];
    __shared__ float Wt[16][HH];

    const int b0  = blockIdx.x * BM;
    const int tid = threadIdx.x;
    const int r_t = tid >> 5;
    const int c_t = tid & 31;

    for (int i = tid; i < BM * HH; i += NTHREADS)
        (&Asm[0][0])[i] = g_last[(size_t)b0 * HH + i];

    float acc[4][8];
    {
        float4 bl = *reinterpret_cast<const float4*>(b1 + c_t * 8);
        float4 bh = *reinterpret_cast<const float4*>(b1 + c_t * 8 + 4);
        float bias[8] = {bl.x, bl.y, bl.z, bl.w, bh.x, bh.y, bh.z, bh.w};
#pragma unroll
        for (int i = 0; i < 4; i++)
#pragma unroll
            for (int j = 0; j < 8; j++) acc[i][j] = bias[j];
    }

    const int kk4   = tid & 3;
    const int cbase = tid >> 2;

    for (int k0 = 0; k0 < HH; k0 += 16) {
        __syncthreads();
#pragma unroll
        for (int q = 0; q < 4; q++) {
            const int c = cbase + 64 * q;
            float4 v = *reinterpret_cast<const float4*>(W1 + (size_t)c * HH + k0 + kk4 * 4);
            Wt[kk4 * 4 + 0][c] = v.x;
            Wt[kk4 * 4 + 1][c] = v.y;
            Wt[kk4 * 4 + 2][c] = v.z;
            Wt[kk4 * 4 + 3][c] = v.w;
        }
        __syncthreads();
#pragma unroll
        for (int kk = 0; kk < 16; kk++) {
            float a[4];
#pragma unroll
            for (int i = 0; i < 4; i++) a[i] = Asm[r_t * 4 + i][k0 + kk];
            float w[8];
            *reinterpret_cast<float4*>(w)     = *reinterpret_cast<const float4*>(&Wt[kk][c_t * 8]);
            *reinterpret_cast<float4*>(w + 4) = *reinterpret_cast<const float4*>(&Wt[kk][c_t * 8 + 4]);
#pragma unroll
            for (int i = 0; i < 4; i++)
#pragma unroll
                for (int j = 0; j < 8; j++) acc[i][j] += a[i] * w[j];
        }
    }
    __syncthreads();

#pragma unroll
    for (int i = 0; i < 4; i++) {
        float yv[8];
#pragma unroll
        for (int j = 0; j < 8; j++) yv[j] = fmaxf(acc[i][j], 0.0f);
        float* yd = &Asm[r_t * 4 + i][c_t * 8];
        *reinterpret_cast<float4*>(yd)     = *reinterpret_cast<float4*>(&yv[0]);
        *reinterpret_cast<float4*>(yd + 4) = *reinterpret_cast<float4*>(&yv[4]);
    }
    __syncthreads();

    for (int e = tid; e < BM * CC; e += NTHREADS) {
        const int r = e / CC;
        const int c = e % CC;
        const float4* yv = reinterpret_cast<const float4*>(&Asm[r][0]);
        const float4* wv = reinterpret_cast<const float4*>(W2 + (size_t)c * HH);
        float s = b2[c];
#pragma unroll 8
        for (int k = 0; k < HH / 4; k++) {
            float4 a = yv[k];
            float4 w = wv[k];
            s += a.x * w.x + a.y * w.y + a.z * w.z + a.w * w.w;
        }
        out[(size_t)(b0 + r) * CC + c] = s;
    }
}

// ---------------------------------------------------------------------------
extern "C" void kernel_launch(void* const* d_in, const int* in_sizes, int n_in,
                              void* d_out, int out_size)
{
    const int*   x_in  = (const int*)  d_in[0];
    const int*   x_len = (const int*)  d_in[1];
    const float* emb   = (const float*)d_in[2];
    const float* W_ih  = (const float*)d_in[3];
    const float* W_hh  = (const float*)d_in[4];
    const float* b_ih  = (const float*)d_in[5];
    const float* b_hh  = (const float*)d_in[6];
    const float* W1    = (const float*)d_in[7];
    const float* b1    = (const float*)d_in[8];
    const float* W2    = (const float*)d_in[9];
    const float* b2    = (const float*)d_in[10];
    float* out = (float*)d_out;

    // opt-in to 96 KB dynamic SMEM for the scan kernel (idempotent)
    cudaFuncSetAttribute(rnn_kernel, cudaFuncAttributeMaxDynamicSharedMemorySize,
                         (BM * HH + 2 * 32 * HH) * (int)sizeof(float));

    transpose_whh_kernel<<<64, NTHREADS>>>(W_hh);
    embw_kernel<<<(VV + BM - 1) / BM, NTHREADS>>>(emb, W_ih, b_ih);
    rnn_kernel<<<BB / BM, NTHREADS, (BM * HH + 2 * 32 * HH) * sizeof(float)>>>(x_in, x_len, b_hh);
    fc_kernel<<<BB / BM, NTHREADS>>>(W1, b1, W2, b2, out);
}